// round 8
// baseline (speedup 1.0000x reference)
#include <cuda_runtime.h>
#include <cstdint>
#include <cstddef>

// FusedAGGemm via mma.sync tf32 (HMMA), round 8.
//   C[M,N] = sum_r A_r[M,KLOC] @ W[r*KLOC:(r+1)*KLOC, N] + bias
// Prepass 1: A -> g_At (flat [M][K], gathered, cvt.rna tf32).
// Prepass 2: W -> g_Wt ([N][K] transpose, cvt.rna tf32).
// GEMM: 128x128 CTA tile, BK=32, 128 threads, 2x2 warp grid (64x64 warp
// tiles -> halves LDS traffic vs 64x32), SW128 smem, cp.async 3-stage,
// 2 CTAs/SM, m16n8k8 tf32 MMA, fp32 accumulators (128 per thread).

#define MDIM 4096
#define KLOC 1024
#define KDIM 8192
#define NDIM 1024

#define BM 128
#define BN 128
#define BK 32
#define NTH 128
#define NTILES (KDIM / BK)   // 256
#define NSTAGE 3

#define SWZ(o) ((o) ^ (((o) >> 3) & 0x70))
#define STAGE_BYTES 32768
#define SM_A(s) ((s) * STAGE_BYTES)
#define SM_B(s) ((s) * STAGE_BYTES + 16384)
#define SMEM_TOTAL (NSTAGE * STAGE_BYTES)   // 98304

__device__ float g_At[(size_t)MDIM * KDIM];   // 128 MB, tf32-rounded, gathered
__device__ float g_Wt[(size_t)NDIM * KDIM];   // 32 MB,  W^T tf32-rounded

// ---------------- helpers ----------------
__device__ __forceinline__ uint32_t smem_u32(const void* p) {
    uint32_t a;
    asm("{ .reg .u64 t; cvta.to.shared.u64 t, %1; cvt.u32.u64 %0, t; }"
        : "=r"(a) : "l"(p));
    return a;
}
__device__ __forceinline__ float4 cvt_tf32x4(float4 v) {
    asm("cvt.rna.tf32.f32 %0, %0;" : "+f"(v.x));
    asm("cvt.rna.tf32.f32 %0, %0;" : "+f"(v.y));
    asm("cvt.rna.tf32.f32 %0, %0;" : "+f"(v.z));
    asm("cvt.rna.tf32.f32 %0, %0;" : "+f"(v.w));
    return v;
}
__device__ __forceinline__ float cvt_tf32(float v) {
    asm("cvt.rna.tf32.f32 %0, %0;" : "+f"(v));
    return v;
}
__device__ __forceinline__ void cp_async16(uint32_t dst, const void* src) {
    asm volatile("cp.async.cg.shared.global [%0], [%1], 16;"
                 :: "r"(dst), "l"(src) : "memory");
}
__device__ __forceinline__ void ldsm4(uint32_t addr, uint32_t* r) {
    asm volatile("ldmatrix.sync.aligned.m8n8.x4.shared.b16 {%0,%1,%2,%3}, [%4];"
                 : "=r"(r[0]), "=r"(r[1]), "=r"(r[2]), "=r"(r[3]) : "r"(addr));
}
__device__ __forceinline__ void mma_tf32(float* c, const uint32_t* a,
                                         uint32_t b0, uint32_t b1) {
    asm volatile(
        "mma.sync.aligned.m16n8k8.row.col.f32.tf32.tf32.f32 "
        "{%0,%1,%2,%3}, {%4,%5,%6,%7}, {%8,%9}, {%0,%1,%2,%3};"
        : "+f"(c[0]), "+f"(c[1]), "+f"(c[2]), "+f"(c[3])
        : "r"(a[0]), "r"(a[1]), "r"(a[2]), "r"(a[3]), "r"(b0), "r"(b1));
}

// ---------------- prepass 1: A -> gathered flat tf32 ----------------
__global__ void prep_A(const float* __restrict__ A) {
    const size_t nf4 = (size_t)MDIM * KDIM / 4;
    for (size_t i = (size_t)blockIdx.x * blockDim.x + threadIdx.x; i < nf4;
         i += (size_t)gridDim.x * blockDim.x) {
        size_t m = i >> 11;
        size_t k = (i & 2047) << 2;
        size_t r = k >> 10, kk = k & (KLOC - 1);
        float4 v = *reinterpret_cast<const float4*>(
            A + ((r * MDIM + m) << 10) + kk);
        *reinterpret_cast<float4*>(&g_At[(m << 13) + k]) = cvt_tf32x4(v);
    }
}

// ---------------- prepass 2: W transpose + tf32 round ----------------
__global__ void prep_W(const float* __restrict__ W) {
    __shared__ float t[32][33];
    const int n0 = blockIdx.x * 32, k0 = blockIdx.y * 32;
    const int tx = threadIdx.x, ty = threadIdx.y;
    #pragma unroll
    for (int j = 0; j < 4; ++j)
        t[ty + 8 * j][tx] = W[(size_t)(k0 + ty + 8 * j) * NDIM + n0 + tx];
    __syncthreads();
    #pragma unroll
    for (int j = 0; j < 4; ++j)
        g_Wt[(size_t)(n0 + ty + 8 * j) * KDIM + k0 + tx] = cvt_tf32(t[tx][ty + 8 * j]);
}

// ---------------- main GEMM ----------------
__global__ __launch_bounds__(NTH, 2)
void ag_gemm_mma(const float* __restrict__ bias, float* __restrict__ C)
{
    extern __shared__ char smem[];
    const uint32_t sb = smem_u32(smem);
    const int tid  = threadIdx.x;
    const int wid  = tid >> 5, lane = tid & 31;
    const int wm   = wid >> 1;          // 0..1 : warp m-half (64 rows)
    const int wn   = wid & 1;           // 0..1 : warp n-half (64 cols)
    const int m0   = blockIdx.y * BM;
    const int n0   = blockIdx.x * BN;

    // ldmatrix per-lane coordinates (fragment mapping validated in R6/R7).
    const uint32_t rowA = (uint32_t)(wm * 64 + (lane & 15));
    const uint32_t kA16 = (uint32_t)((lane >> 4) * 16);
    const uint32_t rowB = (uint32_t)(wn * 64 + (lane & 7) + ((lane >> 4) << 3));
    const uint32_t kB16 = (uint32_t)(((lane >> 3) & 1) * 16);

    float acc[4][8][4];                 // 128 regs
    #pragma unroll
    for (int i = 0; i < 4; ++i)
        #pragma unroll
        for (int j = 0; j < 8; ++j)
            #pragma unroll
            for (int q = 0; q < 4; ++q) acc[i][j][q] = 0.0f;

    // cp.async coordinates: 16 chunks of 16B per thread per tile (A 8 + B 8).
    const int grow = tid >> 3;          // 0..15 (row base, +16*i)
    const int gcol = tid & 7;           // 16B col group

    auto issue_tile = [&](int kt, int s) {
        const float* Ab = g_At + (size_t)(m0 + grow) * KDIM + kt * BK + gcol * 4;
        const float* Bb = g_Wt + (size_t)(n0 + grow) * KDIM + kt * BK + gcol * 4;
        #pragma unroll
        for (int i = 0; i < 8; ++i) {
            uint32_t o = SWZ((uint32_t)(grow + 16 * i) * 128u + (uint32_t)gcol * 16u);
            cp_async16(sb + SM_A(s) + o, Ab + (size_t)i * 16 * KDIM);
            cp_async16(sb + SM_B(s) + o, Bb + (size_t)i * 16 * KDIM);
        }
        asm volatile("cp.async.commit_group;" ::: "memory");
    };

    auto compute_tile = [&](int s) {
        #pragma unroll
        for (int k8 = 0; k8 < 4; ++k8) {
            uint32_t a[4][4], b[4][4];
            #pragma unroll
            for (int i = 0; i < 4; ++i) {
                uint32_t o = (rowA + 16u * i) * 128u + (uint32_t)k8 * 32u + kA16;
                ldsm4(sb + SM_A(s) + SWZ(o), a[i]);
            }
            #pragma unroll
            for (int j = 0; j < 4; ++j) {
                uint32_t o = (rowB + 16u * j) * 128u + (uint32_t)k8 * 32u + kB16;
                ldsm4(sb + SM_B(s) + SWZ(o), b[j]);
            }
            // b[j] = {b0(n8 2j), b1(n8 2j), b0(n8 2j+1), b1(n8 2j+1)}
            #pragma unroll
            for (int i = 0; i < 4; ++i) {
                #pragma unroll
                for (int jj = 0; jj < 8; ++jj)
                    mma_tf32(acc[i][jj], a[i],
                             b[jj >> 1][(jj & 1) * 2], b[jj >> 1][(jj & 1) * 2 + 1]);
            }
        }
    };

    // ---- 3-stage cp.async pipeline ----
    issue_tile(0, 0);
    issue_tile(1, 1);

    for (int kt = 0; kt < NTILES; ++kt) {
        const int s = kt % NSTAGE;
        asm volatile("cp.async.wait_group 1;" ::: "memory");   // tile kt landed
        __syncthreads();                                       // prev compute done
        if (kt + 2 < NTILES) issue_tile(kt + 2, (kt + 2) % NSTAGE);
        compute_tile(s);
    }

    // ---- epilogue: +bias, float2 stores ----
    const int er = lane >> 2;
    const int ec = (lane & 3) * 2;
    float bx[8], by[8];
    #pragma unroll
    for (int jj = 0; jj < 8; ++jj) {
        const int gn = n0 + wn * 64 + jj * 8 + ec;
        bx[jj] = __ldg(bias + gn);
        by[jj] = __ldg(bias + gn + 1);
    }
    #pragma unroll
    for (int i = 0; i < 4; ++i) {
        const int gm = m0 + wm * 64 + i * 16 + er;
        #pragma unroll
        for (int jj = 0; jj < 8; ++jj) {
            const int gn = n0 + wn * 64 + jj * 8 + ec;
            float2 o0 = { acc[i][jj][0] + bx[jj], acc[i][jj][1] + by[jj] };
            float2 o1 = { acc[i][jj][2] + bx[jj], acc[i][jj][3] + by[jj] };
            *reinterpret_cast<float2*>(C + (size_t)gm * NDIM + gn) = o0;
            *reinterpret_cast<float2*>(C + (size_t)(gm + 8) * NDIM + gn) = o1;
        }
    }
}

extern "C" void kernel_launch(void* const* d_in, const int* in_sizes, int n_in,
                              void* d_out, int out_size)
{
    const float* all_act = (const float*)d_in[0];   // (8, 4096, 1024)
    const float* local_W = (const float*)d_in[1];   // (8192, 1024)
    const float* bias    = (const float*)d_in[2];   // (1024,)
    float* out = (float*)d_out;                     // (4096, 1024)

    prep_A<<<2048, 256>>>(all_act);
    prep_W<<<dim3(NDIM / 32, KDIM / 32), dim3(32, 8)>>>(local_W);

    cudaFuncSetAttribute(ag_gemm_mma,
                         cudaFuncAttributeMaxDynamicSharedMemorySize, SMEM_TOTAL);
    dim3 grid(NDIM / BN, MDIM / BM);   // (8, 32) = 256 CTAs
    ag_gemm_mma<<<grid, NTH, SMEM_TOTAL>>>(bias, out);
}

// round 9
// speedup vs baseline: 1.9190x; 1.9190x over previous
#include <cuda_runtime.h>
#include <cuda_fp16.h>
#include <cstdint>
#include <cstddef>

// FusedAGGemm via mma.sync fp16 (HMMA m16n8k16, fp32 accum), round 9.
//   C[M,N] = sum_r A_r[M,KLOC] @ W[r*K:(r+1)*K rows] + bias
// fp16 has the SAME 10-bit mantissa as tf32 (tf32 run measured 2.06e-4),
// data is N(0,1)-scaled -> well inside fp16 range. 2x MMA throughput,
// half the smem/LDSM/cp.async bytes per unit K.
// Prepass 1: A -> g_At (flat [M][K], gathered, fp16).
// Prepass 2: W -> g_Wt ([N][K] transpose, fp16).
// GEMM: 128x128 CTA tile, BK=64 (fp16: 128B rows, SW128), 256 threads,
// 2x4 warp grid (validated R7 shape), cp.async 3-stage, 2 CTAs/SM.

#define MDIM 4096
#define KLOC 1024
#define KDIM 8192
#define NDIM 1024

#define BM 128
#define BN 128
#define BK 64                 // fp16: 64 elems = 128 bytes/row
#define NTH 256
#define NTILES (KDIM / BK)    // 128
#define NSTAGE 3

#define SWZ(o) ((o) ^ (((o) >> 3) & 0x70))
#define STAGE_BYTES 32768
#define SM_A(s) ((s) * STAGE_BYTES)
#define SM_B(s) ((s) * STAGE_BYTES + 16384)
#define SMEM_TOTAL (NSTAGE * STAGE_BYTES)   // 98304

__device__ __half g_At[(size_t)MDIM * KDIM];   // 64 MB, gathered fp16
__device__ __half g_Wt[(size_t)NDIM * KDIM];   // 16 MB, W^T fp16

// ---------------- helpers ----------------
__device__ __forceinline__ uint32_t smem_u32(const void* p) {
    uint32_t a;
    asm("{ .reg .u64 t; cvta.to.shared.u64 t, %1; cvt.u32.u64 %0, t; }"
        : "=r"(a) : "l"(p));
    return a;
}
__device__ __forceinline__ void cp_async16(uint32_t dst, const void* src) {
    asm volatile("cp.async.cg.shared.global [%0], [%1], 16;"
                 :: "r"(dst), "l"(src) : "memory");
}
__device__ __forceinline__ void ldsm4(uint32_t addr, uint32_t* r) {
    asm volatile("ldmatrix.sync.aligned.m8n8.x4.shared.b16 {%0,%1,%2,%3}, [%4];"
                 : "=r"(r[0]), "=r"(r[1]), "=r"(r[2]), "=r"(r[3]) : "r"(addr));
}
__device__ __forceinline__ void mma_f16(float* c, const uint32_t* a,
                                        uint32_t b0, uint32_t b1) {
    asm volatile(
        "mma.sync.aligned.m16n8k16.row.col.f32.f16.f16.f32 "
        "{%0,%1,%2,%3}, {%4,%5,%6,%7}, {%8,%9}, {%0,%1,%2,%3};"
        : "+f"(c[0]), "+f"(c[1]), "+f"(c[2]), "+f"(c[3])
        : "r"(a[0]), "r"(a[1]), "r"(a[2]), "r"(a[3]), "r"(b0), "r"(b1));
}

// ---------------- prepass 1: A -> gathered flat fp16 ----------------
__global__ void prep_A(const float* __restrict__ A) {
    const size_t nf4 = (size_t)MDIM * KDIM / 4;   // 8M float4
    for (size_t i = (size_t)blockIdx.x * blockDim.x + threadIdx.x; i < nf4;
         i += (size_t)gridDim.x * blockDim.x) {
        size_t m = i >> 11;            // 2048 float4 per row
        size_t k = (i & 2047) << 2;
        size_t r = k >> 10, kk = k & (KLOC - 1);
        float4 v = *reinterpret_cast<const float4*>(
            A + ((r * MDIM + m) << 10) + kk);
        __half2 h0 = __floats2half2_rn(v.x, v.y);
        __half2 h1 = __floats2half2_rn(v.z, v.w);
        *reinterpret_cast<__half2*>(&g_At[(m << 13) + k])     = h0;
        *reinterpret_cast<__half2*>(&g_At[(m << 13) + k + 2]) = h1;
    }
}

// ---------------- prepass 2: W transpose + fp16 ----------------
__global__ void prep_W(const float* __restrict__ W) {
    __shared__ float t[32][33];
    const int n0 = blockIdx.x * 32, k0 = blockIdx.y * 32;
    const int tx = threadIdx.x, ty = threadIdx.y;
    #pragma unroll
    for (int j = 0; j < 4; ++j)
        t[ty + 8 * j][tx] = W[(size_t)(k0 + ty + 8 * j) * NDIM + n0 + tx];
    __syncthreads();
    #pragma unroll
    for (int j = 0; j < 4; ++j)
        g_Wt[(size_t)(n0 + ty + 8 * j) * KDIM + k0 + tx] =
            __float2half_rn(t[tx][ty + 8 * j]);
}

// ---------------- main GEMM ----------------
__global__ __launch_bounds__(NTH, 2)
void ag_gemm_mma(const float* __restrict__ bias, float* __restrict__ C)
{
    extern __shared__ char smem[];
    const uint32_t sb = smem_u32(smem);
    const int tid  = threadIdx.x;
    const int wid  = tid >> 5, lane = tid & 31;
    const int wm   = wid >> 2;          // 0..1 : warp m-half (64 rows)
    const int wn   = wid & 3;           // 0..3 : warp n-quarter (32 cols)
    const int m0   = blockIdx.y * BM;
    const int n0   = blockIdx.x * BN;

    // ldmatrix per-lane coords — identical b16 tile mapping to R6/R7.
    const uint32_t rowA = (uint32_t)(wm * 64 + (lane & 15));
    const uint32_t kA16 = (uint32_t)((lane >> 4) * 16);
    const uint32_t rowB = (uint32_t)(wn * 32 + (lane & 7) + ((lane >> 4) << 3));
    const uint32_t kB16 = (uint32_t)(((lane >> 3) & 1) * 16);

    float acc[4][4][4];                 // 64 regs
    #pragma unroll
    for (int i = 0; i < 4; ++i)
        #pragma unroll
        for (int j = 0; j < 4; ++j)
            #pragma unroll
            for (int q = 0; q < 4; ++q) acc[i][j][q] = 0.0f;

    // cp.async: A tile 16KB + B tile 16KB, 256 threads -> 8 x 16B each.
    const int grow = tid >> 3;          // 0..31 (row base, +32*i)
    const int gcol = tid & 7;           // 16B col group (8 fp16)

    auto issue_tile = [&](int kt, int s) {
        const __half* Ab = g_At + (size_t)(m0 + grow) * KDIM + kt * BK + gcol * 8;
        const __half* Bb = g_Wt + (size_t)(n0 + grow) * KDIM + kt * BK + gcol * 8;
        #pragma unroll
        for (int i = 0; i < 4; ++i) {
            uint32_t o = SWZ((uint32_t)(grow + 32 * i) * 128u + (uint32_t)gcol * 16u);
            cp_async16(sb + SM_A(s) + o, Ab + (size_t)i * 32 * KDIM);
            cp_async16(sb + SM_B(s) + o, Bb + (size_t)i * 32 * KDIM);
        }
        asm volatile("cp.async.commit_group;" ::: "memory");
    };

    auto compute_tile = [&](int s) {
        #pragma unroll
        for (int k16 = 0; k16 < 4; ++k16) {       // BK=64 / 16
            uint32_t a[4][4], b[2][4];
            #pragma unroll
            for (int i = 0; i < 4; ++i) {
                uint32_t o = (rowA + 16u * i) * 128u + (uint32_t)k16 * 32u + kA16;
                ldsm4(sb + SM_A(s) + SWZ(o), a[i]);
            }
            #pragma unroll
            for (int j = 0; j < 2; ++j) {
                uint32_t o = (rowB + 16u * j) * 128u + (uint32_t)k16 * 32u + kB16;
                ldsm4(sb + SM_B(s) + SWZ(o), b[j]);
            }
            // b[j] = {b0(n8 2j), b1(n8 2j), b0(n8 2j+1), b1(n8 2j+1)}
            #pragma unroll
            for (int i = 0; i < 4; ++i) {
                #pragma unroll
                for (int jj = 0; jj < 4; ++jj)
                    mma_f16(acc[i][jj], a[i],
                            b[jj >> 1][(jj & 1) * 2], b[jj >> 1][(jj & 1) * 2 + 1]);
            }
        }
    };

    // ---- 3-stage cp.async pipeline ----
    issue_tile(0, 0);
    issue_tile(1, 1);

    for (int kt = 0; kt < NTILES; ++kt) {
        const int s = kt % NSTAGE;
        asm volatile("cp.async.wait_group 1;" ::: "memory");   // tile kt landed
        __syncthreads();                                       // prev compute done
        if (kt + 2 < NTILES) issue_tile(kt + 2, (kt + 2) % NSTAGE);
        compute_tile(s);
    }

    // ---- epilogue: +bias, float2 stores ----
    const int er = lane >> 2;
    const int ec = (lane & 3) * 2;
    #pragma unroll
    for (int i = 0; i < 4; ++i) {
        const int gm = m0 + wm * 64 + i * 16 + er;
        #pragma unroll
        for (int jj = 0; jj < 4; ++jj) {
            const int gn = n0 + wn * 32 + jj * 8 + ec;
            const float bx = __ldg(bias + gn);
            const float by = __ldg(bias + gn + 1);
            float2 o0 = { acc[i][jj][0] + bx, acc[i][jj][1] + by };
            float2 o1 = { acc[i][jj][2] + bx, acc[i][jj][3] + by };
            *reinterpret_cast<float2*>(C + (size_t)gm * NDIM + gn) = o0;
            *reinterpret_cast<float2*>(C + (size_t)(gm + 8) * NDIM + gn) = o1;
        }
    }
}

extern "C" void kernel_launch(void* const* d_in, const int* in_sizes, int n_in,
                              void* d_out, int out_size)
{
    const float* all_act = (const float*)d_in[0];   // (8, 4096, 1024)
    const float* local_W = (const float*)d_in[1];   // (8192, 1024)
    const float* bias    = (const float*)d_in[2];   // (1024,)
    float* out = (float*)d_out;                     // (4096, 1024)

    prep_A<<<2048, 256>>>(all_act);
    prep_W<<<dim3(NDIM / 32, KDIM / 32), dim3(32, 8)>>>(local_W);

    cudaFuncSetAttribute(ag_gemm_mma,
                         cudaFuncAttributeMaxDynamicSharedMemorySize, SMEM_TOTAL);
    dim3 grid(NDIM / BN, MDIM / BM);   // (8, 32) = 256 CTAs
    ag_gemm_mma<<<grid, NTH, SMEM_TOTAL>>>(bias, out);
}